// round 2
// baseline (speedup 1.0000x reference)
#include <cuda_runtime.h>
#include <cuda_bf16.h>

// Reduced Longformer: output depends only on position-0 global attention path.
// B=2, S=4096, DM=768, H=12, HD=64, OUT=512.

#define BB  2
#define SS  4096
#define DMM 768
#define HH  12

// ---------------- scratch (device globals; no allocation allowed) ----------
__device__ float g_qg0[BB * DMM];          // (x[b,0]@Wqg + bqg)*0.125
__device__ float g_C[BB][DMM][HH];         // folded Wkg @ qg0
__device__ float g_d0[BB][HH];             // bkg . qg0 per head
__device__ float g_scores[BB][SS][HH];     // raw attention scores
__device__ float g_mx[BB][HH];
__device__ float g_isum[BB][HH];
__device__ float g_y[BB][HH][DMM];         // softmax-weighted sum of x rows
__device__ float g_out0[BB * DMM];         // attention output at pos 0
__device__ float g_attn0[BB * DMM];        // @Wo + bo
__device__ float g_pooled[BB * DMM];       // @Wp + bp  (tanh applied by consumer)

// FMA macro: acc[0..11] += xs * {r0,r1,r2} (three float4 = 12 coeffs)
#define ROW12(xs, r0, r1, r2)                                                   \
  acc[0] = fmaf(xs, r0.x, acc[0]);  acc[1] = fmaf(xs, r0.y, acc[1]);            \
  acc[2] = fmaf(xs, r0.z, acc[2]);  acc[3] = fmaf(xs, r0.w, acc[3]);            \
  acc[4] = fmaf(xs, r1.x, acc[4]);  acc[5] = fmaf(xs, r1.y, acc[5]);            \
  acc[6] = fmaf(xs, r1.z, acc[6]);  acc[7] = fmaf(xs, r1.w, acc[7]);            \
  acc[8] = fmaf(xs, r2.x, acc[8]);  acc[9] = fmaf(xs, r2.y, acc[9]);            \
  acc[10] = fmaf(xs, r2.z, acc[10]); acc[11] = fmaf(xs, r2.w, acc[11]);

// ---------------- K0: zero accumulators + output ---------------------------
__global__ void k_zero(float* __restrict__ dout) {
  int i = blockIdx.x * 256 + threadIdx.x;           // grid 72*256 = 18432
  (&g_y[0][0][0])[i] = 0.f;
  if (i < BB * DMM) {
    g_qg0[i] = 0.f; g_out0[i] = 0.f; g_attn0[i] = 0.f; g_pooled[i] = 0.f;
  }
  if (i < BB * 512) dout[i] = 0.f;
}

// ---------------- K1: qg0 = (x[b,0] @ Wqg + bqg) * 0.125 -------------------
// grid (2, 6, 3): b, 128-col chunk, 256-row d-split. block 128.
__global__ void k_qg0(const float* __restrict__ x, const float* __restrict__ wqg,
                      const float* __restrict__ bqg) {
  int b = blockIdx.x, dp = blockIdx.y * 128 + threadIdx.x, di = blockIdx.z;
  __shared__ float xv[256];
  const float* xr = x + (size_t)b * SS * DMM + di * 256;
  for (int i = threadIdx.x; i < 256; i += 128) xv[i] = xr[i];
  __syncthreads();
  float acc = 0.f;
  const float* Wc = wqg + (size_t)(di * 256) * DMM + dp;
#pragma unroll 8
  for (int d = 0; d < 256; d++) acc = fmaf(xv[d], __ldg(&Wc[(size_t)d * DMM]), acc);
  if (di == 0) acc += bqg[dp];
  atomicAdd(&g_qg0[b * DMM + dp], acc * 0.125f);
}

// ---------------- K2: C[b][d][h] = Wkg[d, h*64 + j] . qg0[b, h*64 + j] -----
// grid (2, 6), block 128: thread owns one row d.
__global__ void k_C(const float* __restrict__ wkg, const float* __restrict__ bkg) {
  int b = blockIdx.x, d = blockIdx.y * 128 + threadIdx.x;
  __shared__ float q[DMM];
  for (int i = threadIdx.x; i < DMM; i += 128) q[i] = g_qg0[b * DMM + i];
  __syncthreads();
  const float* wrow = wkg + (size_t)d * DMM;
#pragma unroll
  for (int h = 0; h < HH; h++) {
    const float4* w4 = (const float4*)(wrow + h * 64);
    const float* qh = &q[h * 64];
    float a = 0.f;
#pragma unroll
    for (int p = 0; p < 16; p++) {
      float4 w = __ldg(&w4[p]);
      a = fmaf(w.x, qh[p * 4 + 0], a); a = fmaf(w.y, qh[p * 4 + 1], a);
      a = fmaf(w.z, qh[p * 4 + 2], a); a = fmaf(w.w, qh[p * 4 + 3], a);
    }
    g_C[b][d][h] = a;
  }
  if (blockIdx.y == 0 && threadIdx.x < HH) {
    int h = threadIdx.x; float s = 0.f;
    for (int j = 0; j < 64; j++) s = fmaf(bkg[h * 64 + j], q[h * 64 + j], s);
    g_d0[b][h] = s;
  }
}

// ---------------- K3: scores[b][s][h] = x[b,s] . C[b,:,h] + d0 -------------
// grid (2, 64) blocks of 256 threads = 64 s-rows x 4 d-splits (shfl-reduced).
__global__ void __launch_bounds__(256, 4) k_scores(const float* __restrict__ x) {
  int b = blockIdx.x, t = threadIdx.x;
  int half = t & 3, sl = t >> 2;
  int s = blockIdx.y * 64 + sl;
  __shared__ float Cs[DMM * HH];                     // 36 KB
  const float* Cg = &g_C[b][0][0];
  for (int i = t; i < DMM * HH; i += 256) Cs[i] = Cg[i];
  __syncthreads();
  const float4* xr = (const float4*)(x + ((size_t)b * SS + s) * DMM + half * 192);
  const float* cb = &Cs[(half * 192) * HH];
  float acc[12];
#pragma unroll
  for (int h = 0; h < 12; h++) acc[h] = 0.f;
#pragma unroll 4
  for (int p = 0; p < 48; p++) {
    float4 xv = __ldg(&xr[p]);
    const float4* c4 = (const float4*)(cb + p * 48);
    float4 a0 = c4[0], a1 = c4[1], a2 = c4[2];
    float4 b0 = c4[3], b1 = c4[4], b2 = c4[5];
    float4 e0 = c4[6], e1 = c4[7], e2 = c4[8];
    float4 f0 = c4[9], f1 = c4[10], f2 = c4[11];
    ROW12(xv.x, a0, a1, a2)
    ROW12(xv.y, b0, b1, b2)
    ROW12(xv.z, e0, e1, e2)
    ROW12(xv.w, f0, f1, f2)
  }
#pragma unroll
  for (int h = 0; h < 12; h++) {
    acc[h] += __shfl_xor_sync(0xffffffffu, acc[h], 1);
    acc[h] += __shfl_xor_sync(0xffffffffu, acc[h], 2);
  }
  if (half == 0) {
#pragma unroll
    for (int h = 0; h < 12; h++) g_scores[b][s][h] = acc[h] + g_d0[b][h];
  }
}

// ---------------- K4: per-(b,h) softmax max + 1/sum ------------------------
__global__ void k_stats() {
  int b = blockIdx.x / HH, h = blockIdx.x % HH, t = threadIdx.x;
  __shared__ float red[256];
  float m = -1e30f;
  for (int s = t; s < SS; s += 256) m = fmaxf(m, g_scores[b][s][h]);
  red[t] = m; __syncthreads();
  for (int o = 128; o; o >>= 1) { if (t < o) red[t] = fmaxf(red[t], red[t + o]); __syncthreads(); }
  float M = red[0]; __syncthreads();
  float sum = 0.f;
  for (int s = t; s < SS; s += 256) sum += __expf(g_scores[b][s][h] - M);
  red[t] = sum; __syncthreads();
  for (int o = 128; o; o >>= 1) { if (t < o) red[t] += red[t + o]; __syncthreads(); }
  if (t == 0) { g_mx[b][h] = M; g_isum[b][h] = 1.0f / red[0]; }
}

// ---------------- K5: y[b][h][d] += sum_s p[b,h,s] * x[b,s,d] --------------
// grid (3 d-chunks, 32 s-chunks, 2 b), block 256.
__global__ void __launch_bounds__(256, 4) k_y(const float* __restrict__ x) {
  int di = blockIdx.x, si = blockIdx.y, b = blockIdx.z, t = threadIdx.x;
  __shared__ float ps[128][12];
  for (int i = t; i < 128 * 12; i += 256) {
    int r = i / 12, h = i % 12;
    ps[r][h] = __expf(g_scores[b][si * 128 + r][h] - g_mx[b][h]) * g_isum[b][h];
  }
  __syncthreads();
  int d = di * 256 + t;
  float acc[12];
#pragma unroll
  for (int h = 0; h < 12; h++) acc[h] = 0.f;
  const float* xp = x + ((size_t)b * SS + si * 128) * DMM + d;
#pragma unroll 2
  for (int r = 0; r < 128; r++) {
    float xv = __ldg(&xp[(size_t)r * DMM]);
    const float4* pr = (const float4*)ps[r];
    float4 p0 = pr[0], p1 = pr[1], p2 = pr[2];
    ROW12(xv, p0, p1, p2)
  }
#pragma unroll
  for (int h = 0; h < 12; h++) atomicAdd(&g_y[b][h][d], acc[h]);
}

// ---------------- K6: out0[b][h*64+e] = y[b][h] . Wvg[:, h*64+e] + bvg -----
// grid (2, 6, 3), block 128.
__global__ void k_out0(const float* __restrict__ wvg, const float* __restrict__ bvg) {
  int b = blockIdx.x, e = blockIdx.y * 128 + threadIdx.x, di = blockIdx.z;
  __shared__ float yv[512];
  int h0 = blockIdx.y * 2;
  for (int i = threadIdx.x; i < 512; i += 128) {
    int hh = i >> 8, dd = i & 255;
    yv[i] = g_y[b][h0 + hh][di * 256 + dd];
  }
  __syncthreads();
  const float* yr = &yv[((threadIdx.x >> 6) & 1) * 256];
  float acc = 0.f;
  const float* Wc = wvg + (size_t)(di * 256) * DMM + e;
#pragma unroll 8
  for (int d = 0; d < 256; d++) acc = fmaf(yr[d], __ldg(&Wc[(size_t)d * DMM]), acc);
  if (di == 0) acc += bvg[e];
  atomicAdd(&g_out0[b * DMM + e], acc);
}

// ---------------- K7-K9: generic d-split GEMV (optional tanh on input) -----
// grid (B, N/128, 3), block 128. out[b*N + n] += partial.
__global__ void k_gemv(const float* __restrict__ in, const float* __restrict__ W,
                       const float* __restrict__ bias, float* __restrict__ out,
                       int N, int tanhIn) {
  int b = blockIdx.x, n = blockIdx.y * 128 + threadIdx.x, di = blockIdx.z;
  __shared__ float v[256];
  for (int i = threadIdx.x; i < 256; i += 128) {
    float tv = in[b * DMM + di * 256 + i];
    v[i] = tanhIn ? tanhf(tv) : tv;
  }
  __syncthreads();
  float acc = 0.f;
  const float* Wc = W + (size_t)(di * 256) * N + n;
#pragma unroll 8
  for (int d = 0; d < 256; d++) acc = fmaf(v[d], __ldg(&Wc[(size_t)d * N]), acc);
  if (di == 0) acc += bias[n];
  atomicAdd(&out[b * N + n], acc);
}

extern "C" void kernel_launch(void* const* d_in, const int* in_sizes, int n_in,
                              void* d_out, int out_size) {
  const float* x   = (const float*)d_in[0];
  const float* wqg = (const float*)d_in[7];
  const float* bqg = (const float*)d_in[8];
  const float* wkg = (const float*)d_in[9];
  const float* bkg = (const float*)d_in[10];
  const float* wvg = (const float*)d_in[11];
  const float* bvg = (const float*)d_in[12];
  const float* wo  = (const float*)d_in[13];
  const float* bo  = (const float*)d_in[14];
  const float* wp  = (const float*)d_in[15];
  const float* bp  = (const float*)d_in[16];
  const float* wfc = (const float*)d_in[17];
  const float* bfc = (const float*)d_in[18];
  float* out = (float*)d_out;

  void *p_out0 = 0, *p_attn0 = 0, *p_pooled = 0;
  cudaGetSymbolAddress(&p_out0, g_out0);
  cudaGetSymbolAddress(&p_attn0, g_attn0);
  cudaGetSymbolAddress(&p_pooled, g_pooled);

  k_zero<<<72, 256>>>(out);
  k_qg0<<<dim3(2, 6, 3), 128>>>(x, wqg, bqg);
  k_C<<<dim3(2, 6), 128>>>(wkg, bkg);
  k_scores<<<dim3(2, 64), 256>>>(x);
  k_stats<<<24, 256>>>();
  k_y<<<dim3(3, 32, 2), 256>>>(x);
  k_out0<<<dim3(2, 6, 3), 128>>>(wvg, bvg);
  k_gemv<<<dim3(2, 6, 3), 128>>>((const float*)p_out0, wo, bo, (float*)p_attn0, 768, 0);
  k_gemv<<<dim3(2, 6, 3), 128>>>((const float*)p_attn0, wp, bp, (float*)p_pooled, 768, 0);
  k_gemv<<<dim3(2, 4, 3), 128>>>((const float*)p_pooled, wfc, bfc, out, 512, 1);
}

// round 4
// speedup vs baseline: 1.3261x; 1.3261x over previous
#include <cuda_runtime.h>
#include <cuda_bf16.h>

// Reduced Longformer: output depends only on position-0 global attention path.
// B=2, S=4096, DM=768, H=12, HD=64, OUT=512.

#define BB  2
#define SS  4096
#define DMM 768
#define HH  12

// ---------------- scratch (device globals; no allocation allowed) ----------
__device__ float g_qg0[BB * DMM];          // (x[b,0]@Wqg + bqg)*0.125
__device__ float g_C[BB][DMM][HH];         // folded Wkg @ qg0
__device__ float g_d0[BB][HH];             // bkg . qg0 per head
__device__ float g_scores[BB][SS][HH];     // raw attention scores (atomic-accum)
__device__ float g_mx[BB][HH];
__device__ float g_isum[BB][HH];
__device__ float g_y[BB][HH][DMM];         // softmax-weighted sum of x rows
__device__ float g_out0[BB * DMM];         // attention output at pos 0
__device__ float g_attn0[BB * DMM];        // @Wo + bo
__device__ float g_pooled[BB * DMM];       // @Wp + bp  (tanh applied by consumer)

// ---------------- K0: zero accumulators + output ---------------------------
// grid 512x256 = 131072 threads; covers g_scores (98304) + the small buffers.
__global__ void k_zero(float* __restrict__ dout) {
  int i = blockIdx.x * 256 + threadIdx.x;
  if (i < BB * SS * HH) (&g_scores[0][0][0])[i] = 0.f;
  if (i < BB * HH * DMM) (&g_y[0][0][0])[i] = 0.f;
  if (i < BB * DMM) {
    g_qg0[i] = 0.f; g_out0[i] = 0.f; g_attn0[i] = 0.f; g_pooled[i] = 0.f;
  }
  if (i < BB * 512) dout[i] = 0.f;
}

// ---------------- K1: qg0 = (x[b,0] @ Wqg + bqg) * 0.125 -------------------
__global__ void k_qg0(const float* __restrict__ x, const float* __restrict__ wqg,
                      const float* __restrict__ bqg) {
  int b = blockIdx.x, dp = blockIdx.y * 128 + threadIdx.x, di = blockIdx.z;
  __shared__ float xv[256];
  const float* xr = x + (size_t)b * SS * DMM + di * 256;
  for (int i = threadIdx.x; i < 256; i += 128) xv[i] = xr[i];
  __syncthreads();
  float acc = 0.f;
  const float* Wc = wqg + (size_t)(di * 256) * DMM + dp;
#pragma unroll 8
  for (int d = 0; d < 256; d++) acc = fmaf(xv[d], __ldg(&Wc[(size_t)d * DMM]), acc);
  if (di == 0) acc += bqg[dp];
  atomicAdd(&g_qg0[b * DMM + dp], acc * 0.125f);
}

// ---------------- K2: C[b][d][h] = Wkg[d, h*64 + j] . qg0[b, h*64 + j] -----
__global__ void k_C(const float* __restrict__ wkg, const float* __restrict__ bkg) {
  int b = blockIdx.x, d = blockIdx.y * 128 + threadIdx.x;
  __shared__ float q[DMM];
  for (int i = threadIdx.x; i < DMM; i += 128) q[i] = g_qg0[b * DMM + i];
  __syncthreads();
  const float* wrow = wkg + (size_t)d * DMM;
#pragma unroll
  for (int h = 0; h < HH; h++) {
    const float4* w4 = (const float4*)(wrow + h * 64);
    const float* qh = &q[h * 64];
    float a = 0.f;
#pragma unroll
    for (int p = 0; p < 16; p++) {
      float4 w = __ldg(&w4[p]);
      a = fmaf(w.x, qh[p * 4 + 0], a); a = fmaf(w.y, qh[p * 4 + 1], a);
      a = fmaf(w.z, qh[p * 4 + 2], a); a = fmaf(w.w, qh[p * 4 + 3], a);
    }
    g_C[b][d][h] = a;
  }
  if (blockIdx.y == 0 && threadIdx.x < HH) {
    int h = threadIdx.x; float s = 0.f;
    for (int j = 0; j < 64; j++) s = fmaf(bkg[h * 64 + j], q[h * 64 + j], s);
    g_d0[b][h] = s;
  }
}

// ---------------- K3: scores += x . C (per d-half) -------------------------
// grid (2 b, 64 s-chunks, 2 d-halves), block 256.
// lane split: l = t&7 owns 48 contiguous d within the 384-d half; g = t>>3
// owns 2 s-rows. C staged in smem with 580-float lane stride (conflict-free).
#define ACC12(A, xs, c0, c1, c2)                                               \
  A[0] = fmaf(xs, c0.x, A[0]);  A[1] = fmaf(xs, c0.y, A[1]);                   \
  A[2] = fmaf(xs, c0.z, A[2]);  A[3] = fmaf(xs, c0.w, A[3]);                   \
  A[4] = fmaf(xs, c1.x, A[4]);  A[5] = fmaf(xs, c1.y, A[5]);                   \
  A[6] = fmaf(xs, c1.z, A[6]);  A[7] = fmaf(xs, c1.w, A[7]);                   \
  A[8] = fmaf(xs, c2.x, A[8]);  A[9] = fmaf(xs, c2.y, A[9]);                   \
  A[10] = fmaf(xs, c2.z, A[10]); A[11] = fmaf(xs, c2.w, A[11]);

__global__ void __launch_bounds__(256) k_scores(const float* __restrict__ x) {
  int b = blockIdx.x, sc = blockIdx.y, dh = blockIdx.z, t = threadIdx.x;
  int l = t & 7, g = t >> 3;
  int s = sc * 64 + g * 2;
  __shared__ float Cs[8 * 580];                       // 18.6 KB, padded chunks
  const float* Cg = &g_C[b][dh * 384][0];             // 4608 contiguous floats
  for (int i = t; i < 8 * 576; i += 256) {
    int ln = i / 576, off = i - ln * 576;
    Cs[ln * 580 + off] = Cg[i];
  }
  __syncthreads();
  const float4* xr0 = (const float4*)(x + ((size_t)b * SS + s) * DMM + dh * 384 + l * 48);
  const float4* xr1 = (const float4*)((const float*)xr0 + DMM);
  const float* cb = &Cs[l * 580];
  float a0[12], a1[12];
#pragma unroll
  for (int h = 0; h < 12; h++) { a0[h] = 0.f; a1[h] = 0.f; }
#pragma unroll
  for (int p = 0; p < 12; p++) {
    float4 x0 = __ldg(&xr0[p]);
    float4 x1 = __ldg(&xr1[p]);
    const float4* c4 = (const float4*)(cb + p * 48);
    {
      float4 c0 = c4[0], c1 = c4[1], c2 = c4[2];
      ACC12(a0, x0.x, c0, c1, c2)  ACC12(a1, x1.x, c0, c1, c2)
    }
    {
      float4 c0 = c4[3], c1 = c4[4], c2 = c4[5];
      ACC12(a0, x0.y, c0, c1, c2)  ACC12(a1, x1.y, c0, c1, c2)
    }
    {
      float4 c0 = c4[6], c1 = c4[7], c2 = c4[8];
      ACC12(a0, x0.z, c0, c1, c2)  ACC12(a1, x1.z, c0, c1, c2)
    }
    {
      float4 c0 = c4[9], c1 = c4[10], c2 = c4[11];
      ACC12(a0, x0.w, c0, c1, c2)  ACC12(a1, x1.w, c0, c1, c2)
    }
  }
#pragma unroll
  for (int h = 0; h < 12; h++) {
    a0[h] += __shfl_xor_sync(0xffffffffu, a0[h], 1);
    a0[h] += __shfl_xor_sync(0xffffffffu, a0[h], 2);
    a0[h] += __shfl_xor_sync(0xffffffffu, a0[h], 4);
    a1[h] += __shfl_xor_sync(0xffffffffu, a1[h], 1);
    a1[h] += __shfl_xor_sync(0xffffffffu, a1[h], 2);
    a1[h] += __shfl_xor_sync(0xffffffffu, a1[h], 4);
  }
  if (l == 0) {
    float* s0 = &g_scores[b][s][0];
    float* s1 = &g_scores[b][s + 1][0];
    if (dh == 0) {
#pragma unroll
      for (int h = 0; h < 12; h++) {
        atomicAdd(&s0[h], a0[h] + g_d0[b][h]);
        atomicAdd(&s1[h], a1[h] + g_d0[b][h]);
      }
    } else {
#pragma unroll
      for (int h = 0; h < 12; h++) {
        atomicAdd(&s0[h], a0[h]);
        atomicAdd(&s1[h], a1[h]);
      }
    }
  }
}

// ---------------- K4: per-(b,h) softmax max + 1/sum ------------------------
__global__ void k_stats() {
  int b = blockIdx.x / HH, h = blockIdx.x % HH, t = threadIdx.x;
  __shared__ float red[256];
  float m = -1e30f;
  for (int s = t; s < SS; s += 256) m = fmaxf(m, g_scores[b][s][h]);
  red[t] = m; __syncthreads();
  for (int o = 128; o; o >>= 1) { if (t < o) red[t] = fmaxf(red[t], red[t + o]); __syncthreads(); }
  float M = red[0]; __syncthreads();
  float sum = 0.f;
  for (int s = t; s < SS; s += 256) sum += __expf(g_scores[b][s][h] - M);
  red[t] = sum; __syncthreads();
  for (int o = 128; o; o >>= 1) { if (t < o) red[t] += red[t + o]; __syncthreads(); }
  if (t == 0) { g_mx[b][h] = M; g_isum[b][h] = 1.0f / red[0]; }
}

// ---------------- K5: y[b][h][d] += sum_s p[b,h,s] * x[b,s,d] --------------
// grid (64 s-chunks, 2 b), block 192: thread owns 4 d (float4) over 768.
__global__ void __launch_bounds__(192) k_y(const float* __restrict__ x) {
  int sc = blockIdx.x, b = blockIdx.y, t = threadIdx.x;
  __shared__ float ps[64 * 12];
  for (int i = t; i < 64 * 12; i += 192) {
    int r = i / 12, h = i - r * 12;
    ps[i] = __expf(g_scores[b][sc * 64 + r][h] - g_mx[b][h]) * g_isum[b][h];
  }
  __syncthreads();
  float4 acc[12];
#pragma unroll
  for (int h = 0; h < 12; h++) acc[h] = make_float4(0.f, 0.f, 0.f, 0.f);
  const float4* xp = (const float4*)(x + ((size_t)b * SS + sc * 64) * DMM) + t;
#pragma unroll 4
  for (int r = 0; r < 64; r++) {
    float4 xv = __ldg(&xp[(size_t)r * 192]);
    const float4* pr = (const float4*)&ps[r * 12];
    float4 p0 = pr[0], p1 = pr[1], p2 = pr[2];
    const float w[12] = {p0.x, p0.y, p0.z, p0.w, p1.x, p1.y, p1.z, p1.w,
                         p2.x, p2.y, p2.z, p2.w};
#pragma unroll
    for (int h = 0; h < 12; h++) {
      acc[h].x = fmaf(xv.x, w[h], acc[h].x);
      acc[h].y = fmaf(xv.y, w[h], acc[h].y);
      acc[h].z = fmaf(xv.z, w[h], acc[h].z);
      acc[h].w = fmaf(xv.w, w[h], acc[h].w);
    }
  }
  int d = t * 4;
#pragma unroll
  for (int h = 0; h < 12; h++) {
    atomicAdd(&g_y[b][h][d + 0], acc[h].x);
    atomicAdd(&g_y[b][h][d + 1], acc[h].y);
    atomicAdd(&g_y[b][h][d + 2], acc[h].z);
    atomicAdd(&g_y[b][h][d + 3], acc[h].w);
  }
}

// ---------------- K6: out0[b][h*64+e] = y[b][h] . Wvg[:, h*64+e] + bvg -----
__global__ void k_out0(const float* __restrict__ wvg, const float* __restrict__ bvg) {
  int b = blockIdx.x, e = blockIdx.y * 128 + threadIdx.x, di = blockIdx.z;
  __shared__ float yv[512];
  int h0 = blockIdx.y * 2;
  for (int i = threadIdx.x; i < 512; i += 128) {
    int hh = i >> 8, dd = i & 255;
    yv[i] = g_y[b][h0 + hh][di * 256 + dd];
  }
  __syncthreads();
  const float* yr = &yv[((threadIdx.x >> 6) & 1) * 256];
  float acc = 0.f;
  const float* Wc = wvg + (size_t)(di * 256) * DMM + e;
#pragma unroll 8
  for (int d = 0; d < 256; d++) acc = fmaf(yr[d], __ldg(&Wc[(size_t)d * DMM]), acc);
  if (di == 0) acc += bvg[e];
  atomicAdd(&g_out0[b * DMM + e], acc);
}

// ---------------- K7-K9: generic d-split GEMV (optional tanh on input) -----
__global__ void k_gemv(const float* __restrict__ in, const float* __restrict__ W,
                       const float* __restrict__ bias, float* __restrict__ out,
                       int N, int tanhIn) {
  int b = blockIdx.x, n = blockIdx.y * 128 + threadIdx.x, di = blockIdx.z;
  __shared__ float v[256];
  for (int i = threadIdx.x; i < 256; i += 128) {
    float tv = in[b * DMM + di * 256 + i];
    v[i] = tanhIn ? tanhf(tv) : tv;
  }
  __syncthreads();
  float acc = 0.f;
  const float* Wc = W + (size_t)(di * 256) * N + n;
#pragma unroll 8
  for (int d = 0; d < 256; d++) acc = fmaf(v[d], __ldg(&Wc[(size_t)d * N]), acc);
  if (di == 0) acc += bias[n];
  atomicAdd(&out[b * N + n], acc);
}

extern "C" void kernel_launch(void* const* d_in, const int* in_sizes, int n_in,
                              void* d_out, int out_size) {
  const float* x   = (const float*)d_in[0];
  const float* wqg = (const float*)d_in[7];
  const float* bqg = (const float*)d_in[8];
  const float* wkg = (const float*)d_in[9];
  const float* bkg = (const float*)d_in[10];
  const float* wvg = (const float*)d_in[11];
  const float* bvg = (const float*)d_in[12];
  const float* wo  = (const float*)d_in[13];
  const float* bo  = (const float*)d_in[14];
  const float* wp  = (const float*)d_in[15];
  const float* bp  = (const float*)d_in[16];
  const float* wfc = (const float*)d_in[17];
  const float* bfc = (const float*)d_in[18];
  float* out = (float*)d_out;

  void *p_out0 = 0, *p_attn0 = 0, *p_pooled = 0;
  cudaGetSymbolAddress(&p_out0, g_out0);
  cudaGetSymbolAddress(&p_attn0, g_attn0);
  cudaGetSymbolAddress(&p_pooled, g_pooled);

  k_zero<<<512, 256>>>(out);
  k_qg0<<<dim3(2, 6, 3), 128>>>(x, wqg, bqg);
  k_C<<<dim3(2, 6), 128>>>(wkg, bkg);
  k_scores<<<dim3(2, 64, 2), 256>>>(x);
  k_stats<<<24, 256>>>();
  k_y<<<dim3(64, 2), 192>>>(x);
  k_out0<<<dim3(2, 6, 3), 128>>>(wvg, bvg);
  k_gemv<<<dim3(2, 6, 3), 128>>>((const float*)p_out0, wo, bo, (float*)p_attn0, 768, 0);
  k_gemv<<<dim3(2, 6, 3), 128>>>((const float*)p_attn0, wp, bp, (float*)p_pooled, 768, 0);
  k_gemv<<<dim3(2, 4, 3), 128>>>((const float*)p_pooled, wfc, bfc, out, 512, 1);
}

// round 6
// speedup vs baseline: 2.0147x; 1.5192x over previous
#include <cuda_runtime.h>
#include <cuda_bf16.h>

// Reduced Longformer: output depends only on position-0 global attention path.
// B=2, S=4096, DM=768, H=12, HD=64, OUT=512.

#define BB  2
#define SS  4096
#define DMM 768
#define HH  12

// ---------------- scratch (device globals; no allocation allowed) ----------
__device__ float g_qg0[BB * DMM];          // (x[b,0]@Wqg + bqg)*0.125
__device__ float g_C[BB][DMM][HH];         // folded Wkg @ qg0
__device__ float g_d0[BB][HH];             // bkg . qg0 per head
__device__ float g_scores[BB][SS][HH];     // raw attention scores (atomic-accum)
__device__ float g_mx[BB][HH];
__device__ float g_isum[BB][HH];
__device__ float g_y[BB][HH][DMM];         // softmax-weighted sum of x rows
__device__ float g_out0[BB * DMM];         // attention output at pos 0
__device__ float g_attn0[BB * DMM];        // @Wo + bo
__device__ float g_pooled[BB * DMM];       // @Wp + bp  (tanh applied by consumer)

// ---------------- K0: zero accumulators + output ---------------------------
__global__ void k_zero(float* __restrict__ dout) {
  int i = blockIdx.x * 256 + threadIdx.x;           // 512*256 = 131072
  if (i < BB * SS * HH) (&g_scores[0][0][0])[i] = 0.f;
  if (i < BB * HH * DMM) (&g_y[0][0][0])[i] = 0.f;
  if (i < BB * DMM) {
    g_qg0[i] = 0.f; g_out0[i] = 0.f; g_attn0[i] = 0.f; g_pooled[i] = 0.f;
  }
  if (i < BB * 512) dout[i] = 0.f;
}

// ---------------- K1: qg0 = (x[b,0] @ Wqg + bqg) * 0.125 -------------------
// grid (2, 6, 12): b, 128-col chunk, 64-row d-split. block 128.
__global__ void k_qg0(const float* __restrict__ x, const float* __restrict__ wqg,
                      const float* __restrict__ bqg) {
  int b = blockIdx.x, dp = blockIdx.y * 128 + threadIdx.x, di = blockIdx.z;
  __shared__ float xv[64];
  const float* xr = x + (size_t)b * SS * DMM + di * 64;
  if (threadIdx.x < 64) xv[threadIdx.x] = xr[threadIdx.x];
  __syncthreads();
  float acc = 0.f;
  const float* Wc = wqg + (size_t)(di * 64) * DMM + dp;
#pragma unroll 8
  for (int d = 0; d < 64; d++) acc = fmaf(xv[d], __ldg(&Wc[(size_t)d * DMM]), acc);
  if (di == 0) acc += bqg[dp];
  atomicAdd(&g_qg0[b * DMM + dp], acc * 0.125f);
}

// ---------------- K2: C[b][d][h] = Wkg[d, h*64 + j] . qg0[b, h*64 + j] -----
// grid (2, 12), block 256: thread owns (d = by*64 + t>>2, heads (t&3)*3..+2).
__global__ void k_C(const float* __restrict__ wkg, const float* __restrict__ bkg) {
  int b = blockIdx.x, t = threadIdx.x;
  int d = blockIdx.y * 64 + (t >> 2);
  int h0 = (t & 3) * 3;
  __shared__ float q[DMM];
  for (int i = t; i < DMM; i += 256) q[i] = g_qg0[b * DMM + i];
  __syncthreads();
  const float* wrow = wkg + (size_t)d * DMM;
#pragma unroll
  for (int hi = 0; hi < 3; hi++) {
    int h = h0 + hi;
    const float4* w4 = (const float4*)(wrow + h * 64);
    const float* qh = &q[h * 64];
    float a = 0.f;
#pragma unroll
    for (int p = 0; p < 16; p++) {
      float4 w = __ldg(&w4[p]);
      a = fmaf(w.x, qh[p * 4 + 0], a); a = fmaf(w.y, qh[p * 4 + 1], a);
      a = fmaf(w.z, qh[p * 4 + 2], a); a = fmaf(w.w, qh[p * 4 + 3], a);
    }
    g_C[b][d][h] = a;
  }
  if (blockIdx.y == 0 && t < HH) {
    int h = t; float s = 0.f;
    for (int j = 0; j < 64; j++) s = fmaf(bkg[h * 64 + j], q[h * 64 + j], s);
    g_d0[b][h] = s;
  }
}

// ---------------- K3: scores += x . C (per d-quarter) ----------------------
// grid (2 b, 64 s-chunks, 4 d-quarters), block 256.
// lane l = t&7 owns 24 contiguous d within the 192-d quarter; g = t>>3 owns
// 2 s-rows. C staged in smem with 292-float lane stride (conflict-free:
// 292 mod 32 = 4, so 8 lanes occupy disjoint 4-bank groups).
#define ACC12(A, xs, c0, c1, c2)                                               \
  A[0] = fmaf(xs, c0.x, A[0]);  A[1] = fmaf(xs, c0.y, A[1]);                   \
  A[2] = fmaf(xs, c0.z, A[2]);  A[3] = fmaf(xs, c0.w, A[3]);                   \
  A[4] = fmaf(xs, c1.x, A[4]);  A[5] = fmaf(xs, c1.y, A[5]);                   \
  A[6] = fmaf(xs, c1.z, A[6]);  A[7] = fmaf(xs, c1.w, A[7]);                   \
  A[8] = fmaf(xs, c2.x, A[8]);  A[9] = fmaf(xs, c2.y, A[9]);                   \
  A[10] = fmaf(xs, c2.z, A[10]); A[11] = fmaf(xs, c2.w, A[11]);

__global__ void __launch_bounds__(256) k_scores(const float* __restrict__ x) {
  int b = blockIdx.x, sc = blockIdx.y, dh = blockIdx.z, t = threadIdx.x;
  int l = t & 7, g = t >> 3;
  int s = sc * 64 + g * 2;
  __shared__ float Cs[8 * 292];                       // 9.3 KB padded chunks
  const float* Cg = &g_C[b][dh * 192][0];             // 2304 contiguous floats
  for (int i = t; i < 8 * 288; i += 256) {
    int ln = i / 288, off = i - ln * 288;
    Cs[ln * 292 + off] = Cg[i];
  }
  __syncthreads();
  const float4* xr0 = (const float4*)(x + ((size_t)b * SS + s) * DMM + dh * 192 + l * 24);
  const float4* xr1 = (const float4*)((const float*)xr0 + DMM);
  const float* cb = &Cs[l * 292];
  float a0[12], a1[12];
#pragma unroll
  for (int h = 0; h < 12; h++) { a0[h] = 0.f; a1[h] = 0.f; }
#pragma unroll
  for (int p = 0; p < 6; p++) {
    float4 x0 = __ldg(&xr0[p]);
    float4 x1 = __ldg(&xr1[p]);
    const float4* c4 = (const float4*)(cb + p * 48);
    {
      float4 c0 = c4[0], c1 = c4[1], c2 = c4[2];
      ACC12(a0, x0.x, c0, c1, c2)  ACC12(a1, x1.x, c0, c1, c2)
    }
    {
      float4 c0 = c4[3], c1 = c4[4], c2 = c4[5];
      ACC12(a0, x0.y, c0, c1, c2)  ACC12(a1, x1.y, c0, c1, c2)
    }
    {
      float4 c0 = c4[6], c1 = c4[7], c2 = c4[8];
      ACC12(a0, x0.z, c0, c1, c2)  ACC12(a1, x1.z, c0, c1, c2)
    }
    {
      float4 c0 = c4[9], c1 = c4[10], c2 = c4[11];
      ACC12(a0, x0.w, c0, c1, c2)  ACC12(a1, x1.w, c0, c1, c2)
    }
  }
#pragma unroll
  for (int h = 0; h < 12; h++) {
    a0[h] += __shfl_xor_sync(0xffffffffu, a0[h], 1);
    a0[h] += __shfl_xor_sync(0xffffffffu, a0[h], 2);
    a0[h] += __shfl_xor_sync(0xffffffffu, a0[h], 4);
    a1[h] += __shfl_xor_sync(0xffffffffu, a1[h], 1);
    a1[h] += __shfl_xor_sync(0xffffffffu, a1[h], 2);
    a1[h] += __shfl_xor_sync(0xffffffffu, a1[h], 4);
  }
  if (l == 0) {
    float* s0 = &g_scores[b][s][0];
    float* s1 = &g_scores[b][s + 1][0];
    if (dh == 0) {
#pragma unroll
      for (int h = 0; h < 12; h++) {
        atomicAdd(&s0[h], a0[h] + g_d0[b][h]);
        atomicAdd(&s1[h], a1[h] + g_d0[b][h]);
      }
    } else {
#pragma unroll
      for (int h = 0; h < 12; h++) {
        atomicAdd(&s0[h], a0[h]);
        atomicAdd(&s1[h], a1[h]);
      }
    }
  }
}

// ---------------- K4: per-(b,h) softmax max + 1/sum ------------------------
__global__ void k_stats() {
  int b = blockIdx.x / HH, h = blockIdx.x % HH, t = threadIdx.x;
  __shared__ float red[256];
  float m = -1e30f;
  for (int s = t; s < SS; s += 256) m = fmaxf(m, g_scores[b][s][h]);
  red[t] = m; __syncthreads();
  for (int o = 128; o; o >>= 1) { if (t < o) red[t] = fmaxf(red[t], red[t + o]); __syncthreads(); }
  float M = red[0]; __syncthreads();
  float sum = 0.f;
  for (int s = t; s < SS; s += 256) sum += __expf(g_scores[b][s][h] - M);
  red[t] = sum; __syncthreads();
  for (int o = 128; o; o >>= 1) { if (t < o) red[t] += red[t + o]; __syncthreads(); }
  if (t == 0) { g_mx[b][h] = M; g_isum[b][h] = 1.0f / red[0]; }
}

// ---------------- K5: y[b][h][d] += sum_s p[b,h,s] * x[b,s,d] --------------
// grid (64 s-chunks, 2 b), block 384: thread owns float2 of d over 768.
__global__ void __launch_bounds__(384) k_y(const float* __restrict__ x) {
  int sc = blockIdx.x, b = blockIdx.y, t = threadIdx.x;
  __shared__ float ps[64 * 12];
  for (int i = t; i < 64 * 12; i += 384) {
    int r = i / 12, h = i - r * 12;
    ps[i] = __expf(g_scores[b][sc * 64 + r][h] - g_mx[b][h]) * g_isum[b][h];
  }
  __syncthreads();
  float2 acc[12];
#pragma unroll
  for (int h = 0; h < 12; h++) acc[h] = make_float2(0.f, 0.f);
  const float2* xp = (const float2*)(x + ((size_t)b * SS + sc * 64) * DMM) + t;
#pragma unroll 4
  for (int r = 0; r < 64; r++) {
    float2 xv = __ldg(&xp[(size_t)r * 384]);
    const float4* pr = (const float4*)&ps[r * 12];
    float4 p0 = pr[0], p1 = pr[1], p2 = pr[2];
    const float w[12] = {p0.x, p0.y, p0.z, p0.w, p1.x, p1.y, p1.z, p1.w,
                         p2.x, p2.y, p2.z, p2.w};
#pragma unroll
    for (int h = 0; h < 12; h++) {
      acc[h].x = fmaf(xv.x, w[h], acc[h].x);
      acc[h].y = fmaf(xv.y, w[h], acc[h].y);
    }
  }
  int d = t * 2;
#pragma unroll
  for (int h = 0; h < 12; h++) {
    atomicAdd(&g_y[b][h][d + 0], acc[h].x);
    atomicAdd(&g_y[b][h][d + 1], acc[h].y);
  }
}

// ---------------- K6: out0[b][h*64+e] = y[b][h] . Wvg[:, h*64+e] + bvg -----
// grid (2, 6, 6), block 128.
__global__ void k_out0(const float* __restrict__ wvg, const float* __restrict__ bvg) {
  int b = blockIdx.x, e = blockIdx.y * 128 + threadIdx.x, di = blockIdx.z;
  __shared__ float yv[256];
  int h0 = blockIdx.y * 2;
  for (int i = threadIdx.x; i < 256; i += 128) {
    int hh = i >> 7, dd = i & 127;
    yv[i] = g_y[b][h0 + hh][di * 128 + dd];
  }
  __syncthreads();
  const float* yr = &yv[((threadIdx.x >> 6) & 1) * 128];
  float acc = 0.f;
  const float* Wc = wvg + (size_t)(di * 128) * DMM + e;
#pragma unroll 8
  for (int d = 0; d < 128; d++) acc = fmaf(yr[d], __ldg(&Wc[(size_t)d * DMM]), acc);
  if (di == 0) acc += bvg[e];
  atomicAdd(&g_out0[b * DMM + e], acc);
}

// ---------------- K7-K9: generic d-split GEMV (optional tanh on input) -----
// grid (B, N/128, 6), block 128.
__global__ void k_gemv(const float* __restrict__ in, const float* __restrict__ W,
                       const float* __restrict__ bias, float* __restrict__ out,
                       int N, int tanhIn) {
  int b = blockIdx.x, n = blockIdx.y * 128 + threadIdx.x, di = blockIdx.z;
  __shared__ float v[128];
  {
    float tv = in[b * DMM + di * 128 + threadIdx.x];
    v[threadIdx.x] = tanhIn ? tanhf(tv) : tv;
  }
  __syncthreads();
  float acc = 0.f;
  const float* Wc = W + (size_t)(di * 128) * N + n;
#pragma unroll 8
  for (int d = 0; d < 128; d++) acc = fmaf(v[d], __ldg(&Wc[(size_t)d * N]), acc);
  if (di == 0) acc += bias[n];
  atomicAdd(&out[b * N + n], acc);
}

extern "C" void kernel_launch(void* const* d_in, const int* in_sizes, int n_in,
                              void* d_out, int out_size) {
  const float* x   = (const float*)d_in[0];
  const float* wqg = (const float*)d_in[7];
  const float* bqg = (const float*)d_in[8];
  const float* wkg = (const float*)d_in[9];
  const float* bkg = (const float*)d_in[10];
  const float* wvg = (const float*)d_in[11];
  const float* bvg = (const float*)d_in[12];
  const float* wo  = (const float*)d_in[13];
  const float* bo  = (const float*)d_in[14];
  const float* wp  = (const float*)d_in[15];
  const float* bp  = (const float*)d_in[16];
  const float* wfc = (const float*)d_in[17];
  const float* bfc = (const float*)d_in[18];
  float* out = (float*)d_out;

  void *p_out0 = 0, *p_attn0 = 0, *p_pooled = 0;
  cudaGetSymbolAddress(&p_out0, g_out0);
  cudaGetSymbolAddress(&p_attn0, g_attn0);
  cudaGetSymbolAddress(&p_pooled, g_pooled);

  k_zero<<<512, 256>>>(out);
  k_qg0<<<dim3(2, 6, 12), 128>>>(x, wqg, bqg);
  k_C<<<dim3(2, 12), 256>>>(wkg, bkg);
  k_scores<<<dim3(2, 64, 4), 256>>>(x);
  k_stats<<<24, 256>>>();
  k_y<<<dim3(64, 2), 384>>>(x);
  k_out0<<<dim3(2, 6, 6), 128>>>(wvg, bvg);
  k_gemv<<<dim3(2, 6, 6), 128>>>((const float*)p_out0, wo, bo, (float*)p_attn0, 768, 0);
  k_gemv<<<dim3(2, 6, 6), 128>>>((const float*)p_attn0, wp, bp, (float*)p_pooled, 768, 0);
  k_gemv<<<dim3(2, 4, 6), 128>>>((const float*)p_pooled, wfc, bfc, out, 512, 1);
}